// round 4
// baseline (speedup 1.0000x reference)
#include <cuda_runtime.h>
#include <math.h>

#define N_ATOMS 768
#define NM1 767
#define NEDGE (768*767)
#define DIM 64
#define NC 50
#define TABM 768
#define TABRO 512
#define CUTF 5.0f
#define GAPF (5.0f/49.0f)
#define INVH ((float)(TABM-1)/CUTF)
#define INVHRO ((float)(TABRO-1)/CUTF)
#define LN2F 0.69314718055994531f

#define SMEM_MSG ((TABM*DIM + 64*DIM + 64*16)*4)   // table + nw chunk + dist chunk = 217088 B
#define SMEM_UPD ((3*4096 + 3*256 + 64)*4)          // 3 weight mats + sa/st/sh + au2 = 52480 B

// ---- scratch (static device allocations; no runtime alloc) ----
__device__ float g_h[N_ATOMS*DIM];
__device__ float g_nw[N_ATOMS*DIM];
__device__ float g_aggp[3][N_ATOMS*DIM];   // per-i-split partial aggregates
__device__ float g_ha[N_ATOMS];
__device__ float g_tab[3][TABM*DIM];       // e_l(d) tables (biases folded in)
__device__ float g_tabro[TABRO*DIM];       // rbf @ ro_w1[2:52] + ro_b1

__device__ __forceinline__ float sp05(float x){   // Softplus(beta=0.5, thr=14)
    float bx = 0.5f*x;
    return bx > 14.0f ? x : 2.0f*log1pf(expf(bx));
}
__device__ __forceinline__ float sp1(float x){    // Softplus(beta=1, thr=20)
    return x > 20.0f ? x : log1pf(expf(x));
}

// ---- build all interpolation tables exactly (runs once per launch) ----
// blocks [0, TABM): layer tables; blocks [TABM, TABM+TABRO): readout table
__global__ void k_build(const float* __restrict__ pw1, const float* __restrict__ pb1,
                        const float* __restrict__ pw2, const float* __restrict__ pb2,
                        const float* __restrict__ row1, const float* __restrict__ rob1){
    int b = blockIdx.x, c = threadIdx.x;
    __shared__ float rbf[NC], sp[DIM];
    if (b < TABM){
        float d = (float)b * (CUTF/(float)(TABM-1));
        if (c < NC){ float t = d - (float)c*GAPF; rbf[c] = expf(-t*t*(1.0f/GAPF)); }
        __syncthreads();
        for (int l=0;l<3;l++){
            float u = pb1[l*DIM+c];
            #pragma unroll 10
            for (int k=0;k<NC;k++) u = fmaf(rbf[k], pw1[(l*NC+k)*DIM+c], u);
            float s = sp05(u);
            sp[c] = s; __syncthreads();
            float e = pb2[l*DIM+c];
            #pragma unroll 8
            for (int k=0;k<DIM;k++) e = fmaf(sp[k], pw2[(l*DIM+k)*DIM+c], e);
            g_tab[l][b*DIM+c] = e;
            __syncthreads();
        }
    } else {
        int m = b - TABM;
        float d = (float)m * (CUTF/(float)(TABRO-1));
        if (c < NC){ float t = d - (float)c*GAPF; rbf[c] = expf(-t*t*(1.0f/GAPF)); }
        __syncthreads();
        float v = rob1[c];
        #pragma unroll 10
        for (int k=0;k<NC;k++) v = fmaf(rbf[k], row1[(2+k)*DIM+c], v);
        g_tabro[m*DIM+c] = v;
    }
}

// ---- h = embedding[atom_types]; nw = h @ w1[0] ----
__global__ void k_init(const int* __restrict__ at, const float* __restrict__ emb,
                       const float* __restrict__ w1){
    int n = blockIdx.x, c = threadIdx.x;
    __shared__ float sh[DIM];
    float hv = emb[at[n]*DIM + c];
    sh[c] = hv; g_h[n*DIM+c] = hv;
    __syncthreads();
    float a = 0.f;
    #pragma unroll 8
    for (int k=0;k<DIM;k++) a = fmaf(sh[k], w1[k*DIM+c], a);
    g_nw[n*DIM+c] = a;
}

// ---- message pass: aggp[isp][j] = sum_{i in range(isp), i != j} nw[i] * e_l(d_ij)
// grid (48, 3): 16 dst per block, 3-way i-split. Table + nw/dist chunks in smem.
__global__ void __launch_bounds__(256) k_msg(const float* __restrict__ dist, int l){
    extern __shared__ float sm[];
    float*  tab_s  = sm;                              // TABM*64 floats
    float4* nw_s   = (float4*)(sm + TABM*DIM);        // 64*16 float4
    float*  dist_s = sm + TABM*DIM + 64*DIM;          // 64*16 floats

    int tid  = threadIdx.x;
    int grp  = tid >> 4;
    int g    = tid & 15;
    int jbase = blockIdx.x * 16;
    int j     = jbase + grp;
    int isp   = blockIdx.y;

    // stage layer table (192KB) into smem
    const float4* tg = (const float4*)g_tab[l];
    float4* ts4 = (float4*)tab_s;
    for (int k = tid; k < TABM*16; k += 256) ts4[k] = tg[k];

    float4 acc = make_float4(0.f,0.f,0.f,0.f);
    const float4* nwg = (const float4*)g_nw;

    for (int ch = 0; ch < 4; ch++){
        int ibase = isp*256 + ch*64;
        __syncthreads();   // (also covers table staging on first iter)
        // stage nw chunk: 64 rows x 16 float4, coalesced
        for (int k = tid; k < 64*16; k += 256) nw_s[k] = nwg[ibase*16 + k];
        // stage dist chunk: 64 i x 16 j
        for (int s = tid; s < 64*16; s += 256){
            int il = s >> 4, jj = s & 15;
            int i = ibase + il, jd = jbase + jj;
            float dv = 0.f;
            if (i != jd) dv = __ldg(dist + i*NM1 + jd - (jd > i));
            dist_s[s] = dv;
        }
        __syncthreads();
        #pragma unroll 4
        for (int il = 0; il < 64; il++){
            int i = ibase + il;
            if (i == j) continue;
            float d = dist_s[il*16 + grp];
            float x = d * INVH;
            int t = min((int)x, TABM-2);
            float f = x - (float)t;
            const float4* r = (const float4*)tab_s + t*16;
            float4 t0 = r[g];
            float4 t1 = r[16 + g];
            float4 w  = nw_s[il*16 + g];
            acc.x = fmaf(w.x, fmaf(f, t1.x - t0.x, t0.x), acc.x);
            acc.y = fmaf(w.y, fmaf(f, t1.y - t0.y, t0.y), acc.y);
            acc.z = fmaf(w.z, fmaf(f, t1.z - t0.z, t0.z), acc.z);
            acc.w = fmaf(w.w, fmaf(f, t1.w - t0.w, t0.w), acc.w);
        }
    }
    ((float4*)g_aggp[isp])[j*16 + g] = acc;
}

// ---- node update: h += MLP(sum of agg partials); then nw for next layer, or ha ----
// grid 192 x 256 threads: 4 nodes per block, weights staged in smem.
__global__ void __launch_bounds__(256) k_upd(int l, int last,
        const float* __restrict__ qw1, const float* __restrict__ qb1,
        const float* __restrict__ qw2, const float* __restrict__ qb2,
        const float* __restrict__ w1,
        const float* __restrict__ auw1, const float* __restrict__ aub1,
        const float* __restrict__ auw2, const float* __restrict__ aub2){
    extern __shared__ float sm[];
    float* wA  = sm;            // qw1[l]           (4096)
    float* wB  = sm + 4096;     // qw2[l]           (4096)
    float* wC  = sm + 8192;     // w1[l+1] or au_w1 (4096)
    float* sa  = sm + 12288;    // 4 x 64
    float* st  = sm + 12544;    // 4 x 64
    float* sh  = sm + 12800;    // 4 x 64
    float* au2 = sm + 13056;    // 64

    int tid = threadIdx.x;
    int nd  = tid >> 6;
    int c   = tid & 63;
    int n   = blockIdx.x*4 + nd;

    const float* wAs = qw1 + l*DIM*DIM;
    const float* wBs = qw2 + l*DIM*DIM;
    const float* wCs = last ? auw1 : (w1 + (l+1)*DIM*DIM);
    for (int k = tid; k < DIM*DIM; k += 256){
        wA[k] = wAs[k]; wB[k] = wBs[k]; wC[k] = wCs[k];
    }
    if (last && tid < DIM) au2[tid] = auw2[tid];

    float a = g_aggp[0][n*DIM+c] + g_aggp[1][n*DIM+c] + g_aggp[2][n*DIM+c];
    sa[nd*DIM + c] = a;
    __syncthreads();

    float u = qb1[l*DIM+c];
    #pragma unroll 8
    for (int k=0;k<DIM;k++) u = fmaf(sa[nd*DIM+k], wA[k*DIM+c], u);
    st[nd*DIM + c] = sp05(u);
    __syncthreads();

    float up = qb2[l*DIM+c];
    #pragma unroll 8
    for (int k=0;k<DIM;k++) up = fmaf(st[nd*DIM+k], wB[k*DIM+c], up);
    float hn = g_h[n*DIM+c] + up;
    g_h[n*DIM+c] = hn;
    sh[nd*DIM + c] = hn;
    __syncthreads();

    if (!last){
        float a2 = 0.f;
        #pragma unroll 8
        for (int k=0;k<DIM;k++) a2 = fmaf(sh[nd*DIM+k], wC[k*DIM+c], a2);
        g_nw[n*DIM+c] = a2;
    } else {
        float u2 = aub1[c];
        #pragma unroll 8
        for (int k=0;k<DIM;k++) u2 = fmaf(sh[nd*DIM+k], wC[k*DIM+c], u2);
        st[nd*DIM + c] = sp1(u2) - LN2F;
        __syncthreads();
        if (c == 0){
            float acc2 = aub2[0];
            #pragma unroll 8
            for (int k=0;k<DIM;k++) acc2 = fmaf(st[nd*DIM+k], au2[k], acc2);
            g_ha[n] = acc2;
        }
    }
}

// ---- readout: softmax(relu([ha_i, ha_j, rbf] @ ro_w1 + b1) @ ro_w2 + b2) per edge
// small L1-resident readout table (128KB).
__global__ void __launch_bounds__(256) k_readout(const float* __restrict__ dist,
        const float* __restrict__ row1, const float* __restrict__ row2,
        const float* __restrict__ rob2, float* __restrict__ out){
    int g = threadIdx.x & 15;
    float4 wa  = __ldg((const float4*)row1 + g);          // ro_w1 row 0 (ha_src)
    float4 wb  = __ldg((const float4*)(row1 + DIM) + g);  // ro_w1 row 1 (ha_dst)
    float4 w2a = __ldg((const float4*)row2 + 2*g);
    float4 w2b = __ldg((const float4*)row2 + 2*g + 1);
    float b20 = rob2[0], b21 = rob2[1];
    int group   = (blockIdx.x * blockDim.x + threadIdx.x) >> 4;
    int ngroups = (gridDim.x * blockDim.x) >> 4;
    for (int e = group; e < NEDGE; e += ngroups){
        int i = e / NM1;
        int r = e - i*NM1;
        int j = r + (r >= i);
        float d = __ldg(dist + e);
        float x = d * INVHRO;
        int t = min((int)x, TABRO-2);
        float f = x - (float)t;
        const float4* rp = (const float4*)g_tabro + t*16;
        float4 t0 = __ldg(rp + g);
        float4 t1 = __ldg(rp + 16 + g);
        float hi = g_ha[i];
        float hj = g_ha[j];
        float z0 = fmaf(f, t1.x-t0.x, t0.x) + hi*wa.x + hj*wb.x; z0 = fmaxf(z0, 0.f);
        float z1 = fmaf(f, t1.y-t0.y, t0.y) + hi*wa.y + hj*wb.y; z1 = fmaxf(z1, 0.f);
        float z2 = fmaf(f, t1.z-t0.z, t0.z) + hi*wa.z + hj*wb.z; z2 = fmaxf(z2, 0.f);
        float z3 = fmaf(f, t1.w-t0.w, t0.w) + hi*wa.w + hj*wb.w; z3 = fmaxf(z3, 0.f);
        float a0 = z0*w2a.x + z1*w2a.z + z2*w2b.x + z3*w2b.z;
        float a1 = z0*w2a.y + z1*w2a.w + z2*w2b.y + z3*w2b.w;
        #pragma unroll
        for (int off=8; off; off>>=1){
            a0 += __shfl_xor_sync(0xffffffffu, a0, off);
            a1 += __shfl_xor_sync(0xffffffffu, a1, off);
        }
        if (g == 0){
            float l0 = a0 + b20, l1 = a1 + b21;
            float m = fmaxf(l0, l1);
            float e0 = __expf(l0 - m), e1 = __expf(l1 - m);
            float inv = 1.0f/(e0 + e1);
            ((float2*)out)[e] = make_float2(e0*inv, e1*inv);
        }
    }
}

extern "C" void kernel_launch(void* const* d_in, const int* in_sizes, int n_in,
                              void* d_out, int out_size){
    const int*   at   = (const int*)  d_in[0];
    const float* dist = (const float*)d_in[1];
    // d_in[2]=src, d_in[3]=dst (recomputed analytically; complete graph)
    const float* emb  = (const float*)d_in[4];
    const float* w1   = (const float*)d_in[5];
    const float* pw1  = (const float*)d_in[6];
    const float* pb1  = (const float*)d_in[7];
    const float* pw2  = (const float*)d_in[8];
    const float* pb2  = (const float*)d_in[9];
    const float* qw1  = (const float*)d_in[10];
    const float* qb1  = (const float*)d_in[11];
    const float* qw2  = (const float*)d_in[12];
    const float* qb2  = (const float*)d_in[13];
    const float* auw1 = (const float*)d_in[14];
    const float* aub1 = (const float*)d_in[15];
    const float* auw2 = (const float*)d_in[16];
    const float* aub2 = (const float*)d_in[17];
    const float* row1 = (const float*)d_in[18];
    const float* rob1 = (const float*)d_in[19];
    const float* row2 = (const float*)d_in[20];
    const float* rob2 = (const float*)d_in[21];
    float* out = (float*)d_out;

    cudaFuncSetAttribute(k_msg, cudaFuncAttributeMaxDynamicSharedMemorySize, SMEM_MSG);
    cudaFuncSetAttribute(k_upd, cudaFuncAttributeMaxDynamicSharedMemorySize, SMEM_UPD);

    k_build<<<TABM + TABRO, 64>>>(pw1, pb1, pw2, pb2, row1, rob1);
    k_init<<<N_ATOMS, 64>>>(at, emb, w1);
    for (int l = 0; l < 3; l++){
        k_msg<<<dim3(48,3), 256, SMEM_MSG>>>(dist, l);
        k_upd<<<192, 256, SMEM_UPD>>>(l, (l==2) ? 1 : 0, qw1, qb1, qw2, qb2, w1,
                                      auw1, aub1, auw2, aub2);
    }
    k_readout<<<1184, 256>>>(dist, row1, row2, rob2, out);
}

// round 5
// speedup vs baseline: 1.1843x; 1.1843x over previous
#include <cuda_runtime.h>
#include <math.h>

#define N_ATOMS 768
#define NM1 767
#define NEDGE (768*767)
#define DIM 64
#define NC 50
#define TABM 768
#define TABRO 512
#define CUTF 5.0f
#define GAPF (5.0f/49.0f)
#define INVH ((float)(TABM-1)/CUTF)
#define INVHRO ((float)(TABRO-1)/CUTF)
#define LN2F 0.69314718055994531f

#define NSPLIT 6
#define IPB (N_ATOMS/NSPLIT)     // 128 i-rows per block
#define JPB 16                   // 16 dst per block

#define SMEM_UPD ((3*4096 + 3*256 + 64)*4)   // 3 weight mats + sa/st/sh + au2 = 52480 B

// ---- scratch (static device allocations; no runtime alloc) ----
__device__ float g_h[N_ATOMS*DIM];
__device__ float g_nw[N_ATOMS*DIM];
__device__ float g_aggp[NSPLIT][N_ATOMS*DIM];  // per-i-split partial aggregates
__device__ float g_ha[N_ATOMS];
__device__ float g_tab[3][TABM*DIM];           // e_l(d) tables (biases folded in)
__device__ float g_tabro[TABRO*DIM];           // rbf @ ro_w1[2:52] + ro_b1

__device__ __forceinline__ float sp05(float x){   // Softplus(beta=0.5, thr=14)
    float bx = 0.5f*x;
    return bx > 14.0f ? x : 2.0f*log1pf(expf(bx));
}
__device__ __forceinline__ float sp1(float x){    // Softplus(beta=1, thr=20)
    return x > 20.0f ? x : log1pf(expf(x));
}

// ---- build all interpolation tables exactly (runs once per launch) ----
__global__ void k_build(const float* __restrict__ pw1, const float* __restrict__ pb1,
                        const float* __restrict__ pw2, const float* __restrict__ pb2,
                        const float* __restrict__ row1, const float* __restrict__ rob1){
    int b = blockIdx.x, c = threadIdx.x;
    __shared__ float rbf[NC], sp[DIM];
    if (b < TABM){
        float d = (float)b * (CUTF/(float)(TABM-1));
        if (c < NC){ float t = d - (float)c*GAPF; rbf[c] = expf(-t*t*(1.0f/GAPF)); }
        __syncthreads();
        for (int l=0;l<3;l++){
            float u = pb1[l*DIM+c];
            #pragma unroll 10
            for (int k=0;k<NC;k++) u = fmaf(rbf[k], pw1[(l*NC+k)*DIM+c], u);
            float s = sp05(u);
            sp[c] = s; __syncthreads();
            float e = pb2[l*DIM+c];
            #pragma unroll 8
            for (int k=0;k<DIM;k++) e = fmaf(sp[k], pw2[(l*DIM+k)*DIM+c], e);
            g_tab[l][b*DIM+c] = e;
            __syncthreads();
        }
    } else {
        int m = b - TABM;
        float d = (float)m * (CUTF/(float)(TABRO-1));
        if (c < NC){ float t = d - (float)c*GAPF; rbf[c] = expf(-t*t*(1.0f/GAPF)); }
        __syncthreads();
        float v = rob1[c];
        #pragma unroll 10
        for (int k=0;k<NC;k++) v = fmaf(rbf[k], row1[(2+k)*DIM+c], v);
        g_tabro[m*DIM+c] = v;
    }
}

// ---- h = embedding[atom_types]; nw = h @ w1[0] ----
__global__ void k_init(const int* __restrict__ at, const float* __restrict__ emb,
                       const float* __restrict__ w1){
    int n = blockIdx.x, c = threadIdx.x;
    __shared__ float sh[DIM];
    float hv = emb[at[n]*DIM + c];
    sh[c] = hv; g_h[n*DIM+c] = hv;
    __syncthreads();
    float a = 0.f;
    #pragma unroll 8
    for (int k=0;k<DIM;k++) a = fmaf(sh[k], w1[k*DIM+c], a);
    g_nw[n*DIM+c] = a;
}

// ---- message pass: aggp[isp][j] += sum_{i in split, i != j} nw[i] * lerp(tab_l, d_ij)
// grid (48, NSPLIT). nw+dist chunk in smem (reg-batched copy); table via L1 (__ldg).
__global__ void __launch_bounds__(256,2) k_msg(const float* __restrict__ dist, int l){
    __shared__ float4 nw_s[IPB*16];     // 32 KB
    __shared__ float  dist_s[IPB*JPB];  // 8 KB

    int tid  = threadIdx.x;
    int grp  = tid >> 4;         // j within tile
    int g    = tid & 15;         // float4 lane
    int jbase = blockIdx.x * JPB;
    int ibase = blockIdx.y * IPB;
    int j     = jbase + grp;

    // stage nw chunk: fully coalesced, register-batched for MLP
    {
        const float4* __restrict__ nwg = (const float4*)g_nw + ibase*16;
        float4 rn[8];
        #pragma unroll
        for (int q=0;q<8;q++) rn[q] = __ldg(nwg + tid + 256*q);
        #pragma unroll
        for (int q=0;q<8;q++) nw_s[tid + 256*q] = rn[q];
    }
    // stage dist chunk: 128 i x 16 j
    {
        float rd[8];
        #pragma unroll
        for (int q=0;q<8;q++){
            int s = tid + 256*q;
            int il = s >> 4, jj = s & 15;
            int i = ibase + il, jd = jbase + jj;
            rd[q] = (i != jd) ? __ldg(dist + i*NM1 + jd - (jd > i)) : 0.f;
        }
        #pragma unroll
        for (int q=0;q<8;q++) dist_s[tid + 256*q] = rd[q];
    }
    __syncthreads();

    const float4* __restrict__ tab4 = (const float4*)g_tab[l];
    float4 acc = make_float4(0.f,0.f,0.f,0.f);
    #pragma unroll 2
    for (int il = 0; il < IPB; il++){
        int i = ibase + il;
        if (i == j) continue;
        float x = dist_s[il*16 + grp] * INVH;
        int t = min((int)x, TABM-2);
        float f = x - (float)t;
        const float4* r = tab4 + t*16 + g;
        float4 t0 = __ldg(r);
        float4 t1 = __ldg(r + 16);
        float4 w  = nw_s[il*16 + g];
        acc.x = fmaf(w.x, fmaf(f, t1.x - t0.x, t0.x), acc.x);
        acc.y = fmaf(w.y, fmaf(f, t1.y - t0.y, t0.y), acc.y);
        acc.z = fmaf(w.z, fmaf(f, t1.z - t0.z, t0.z), acc.z);
        acc.w = fmaf(w.w, fmaf(f, t1.w - t0.w, t0.w), acc.w);
    }
    ((float4*)g_aggp[blockIdx.y])[j*16 + g] = acc;
}

// ---- node update: h += MLP(sum of agg partials); then nw for next layer, or ha ----
// grid 192 x 256: 4 nodes/block; weights staged in smem with register-batched copy.
__global__ void __launch_bounds__(256) k_upd(int l, int last,
        const float* __restrict__ qw1, const float* __restrict__ qb1,
        const float* __restrict__ qw2, const float* __restrict__ qb2,
        const float* __restrict__ w1,
        const float* __restrict__ auw1, const float* __restrict__ aub1,
        const float* __restrict__ auw2, const float* __restrict__ aub2){
    extern __shared__ float sm[];
    float* wA  = sm;            // qw1[l]           (4096)
    float* wB  = sm + 4096;     // qw2[l]           (4096)
    float* wC  = sm + 8192;     // w1[l+1] or au_w1 (4096)
    float* sa  = sm + 12288;    // 4 x 64
    float* st  = sm + 12544;    // 4 x 64
    float* sh  = sm + 12800;    // 4 x 64
    float* au2 = sm + 13056;    // 64

    int tid = threadIdx.x;
    int nd  = tid >> 6;
    int c   = tid & 63;
    int n   = blockIdx.x*4 + nd;

    // register-batched staging (MLP = 12)
    {
        const float4* A4 = (const float4*)(qw1 + l*DIM*DIM);
        const float4* B4 = (const float4*)(qw2 + l*DIM*DIM);
        const float4* C4 = (const float4*)(last ? auw1 : (w1 + (l+1)*DIM*DIM));
        float4 ra[4], rb[4], rc[4];
        #pragma unroll
        for (int q=0;q<4;q++){
            ra[q] = __ldg(A4 + tid + 256*q);
            rb[q] = __ldg(B4 + tid + 256*q);
            rc[q] = __ldg(C4 + tid + 256*q);
        }
        #pragma unroll
        for (int q=0;q<4;q++){
            ((float4*)wA)[tid + 256*q] = ra[q];
            ((float4*)wB)[tid + 256*q] = rb[q];
            ((float4*)wC)[tid + 256*q] = rc[q];
        }
    }
    if (last && tid < DIM) au2[tid] = auw2[tid];

    int off = n*DIM + c;
    float a = (g_aggp[0][off] + g_aggp[1][off])
            + (g_aggp[2][off] + g_aggp[3][off])
            + (g_aggp[4][off] + g_aggp[5][off]);
    sa[nd*DIM + c] = a;
    __syncthreads();

    float u = qb1[l*DIM+c];
    #pragma unroll 8
    for (int k=0;k<DIM;k++) u = fmaf(sa[nd*DIM+k], wA[k*DIM+c], u);
    st[nd*DIM + c] = sp05(u);
    __syncthreads();

    float up = qb2[l*DIM+c];
    #pragma unroll 8
    for (int k=0;k<DIM;k++) up = fmaf(st[nd*DIM+k], wB[k*DIM+c], up);
    float hn = g_h[off] + up;
    g_h[off] = hn;
    sh[nd*DIM + c] = hn;
    __syncthreads();

    if (!last){
        float a2 = 0.f;
        #pragma unroll 8
        for (int k=0;k<DIM;k++) a2 = fmaf(sh[nd*DIM+k], wC[k*DIM+c], a2);
        g_nw[off] = a2;
    } else {
        float u2 = aub1[c];
        #pragma unroll 8
        for (int k=0;k<DIM;k++) u2 = fmaf(sh[nd*DIM+k], wC[k*DIM+c], u2);
        st[nd*DIM + c] = sp1(u2) - LN2F;
        __syncthreads();
        if (c == 0){
            float acc2 = aub2[0];
            #pragma unroll 8
            for (int k=0;k<DIM;k++) acc2 = fmaf(st[nd*DIM+k], au2[k], acc2);
            g_ha[n] = acc2;
        }
    }
}

// ---- readout: softmax(relu([ha_i, ha_j, rbf] @ ro_w1 + b1) @ ro_w2 + b2) per edge
__global__ void __launch_bounds__(256) k_readout(const float* __restrict__ dist,
        const float* __restrict__ row1, const float* __restrict__ row2,
        const float* __restrict__ rob2, float* __restrict__ out){
    int g = threadIdx.x & 15;
    float4 wa  = __ldg((const float4*)row1 + g);          // ro_w1 row 0 (ha_src)
    float4 wb  = __ldg((const float4*)(row1 + DIM) + g);  // ro_w1 row 1 (ha_dst)
    float4 w2a = __ldg((const float4*)row2 + 2*g);
    float4 w2b = __ldg((const float4*)row2 + 2*g + 1);
    float b20 = rob2[0], b21 = rob2[1];
    int group   = (blockIdx.x * blockDim.x + threadIdx.x) >> 4;
    int ngroups = (gridDim.x * blockDim.x) >> 4;
    for (int e = group; e < NEDGE; e += ngroups){
        int i = e / NM1;
        int r = e - i*NM1;
        int j = r + (r >= i);
        float d = __ldg(dist + e);
        float x = d * INVHRO;
        int t = min((int)x, TABRO-2);
        float f = x - (float)t;
        const float4* rp = (const float4*)g_tabro + t*16;
        float4 t0 = __ldg(rp + g);
        float4 t1 = __ldg(rp + 16 + g);
        float hi = g_ha[i];
        float hj = g_ha[j];
        float z0 = fmaf(f, t1.x-t0.x, t0.x) + hi*wa.x + hj*wb.x; z0 = fmaxf(z0, 0.f);
        float z1 = fmaf(f, t1.y-t0.y, t0.y) + hi*wa.y + hj*wb.y; z1 = fmaxf(z1, 0.f);
        float z2 = fmaf(f, t1.z-t0.z, t0.z) + hi*wa.z + hj*wb.z; z2 = fmaxf(z2, 0.f);
        float z3 = fmaf(f, t1.w-t0.w, t0.w) + hi*wa.w + hj*wb.w; z3 = fmaxf(z3, 0.f);
        float a0 = z0*w2a.x + z1*w2a.z + z2*w2b.x + z3*w2b.z;
        float a1 = z0*w2a.y + z1*w2a.w + z2*w2b.y + z3*w2b.w;
        #pragma unroll
        for (int off=8; off; off>>=1){
            a0 += __shfl_xor_sync(0xffffffffu, a0, off);
            a1 += __shfl_xor_sync(0xffffffffu, a1, off);
        }
        if (g == 0){
            float l0 = a0 + b20, l1 = a1 + b21;
            float m = fmaxf(l0, l1);
            float e0 = __expf(l0 - m), e1 = __expf(l1 - m);
            float inv = 1.0f/(e0 + e1);
            ((float2*)out)[e] = make_float2(e0*inv, e1*inv);
        }
    }
}

extern "C" void kernel_launch(void* const* d_in, const int* in_sizes, int n_in,
                              void* d_out, int out_size){
    const int*   at   = (const int*)  d_in[0];
    const float* dist = (const float*)d_in[1];
    // d_in[2]=src, d_in[3]=dst (recomputed analytically; complete graph)
    const float* emb  = (const float*)d_in[4];
    const float* w1   = (const float*)d_in[5];
    const float* pw1  = (const float*)d_in[6];
    const float* pb1  = (const float*)d_in[7];
    const float* pw2  = (const float*)d_in[8];
    const float* pb2  = (const float*)d_in[9];
    const float* qw1  = (const float*)d_in[10];
    const float* qb1  = (const float*)d_in[11];
    const float* qw2  = (const float*)d_in[12];
    const float* qb2  = (const float*)d_in[13];
    const float* auw1 = (const float*)d_in[14];
    const float* aub1 = (const float*)d_in[15];
    const float* auw2 = (const float*)d_in[16];
    const float* aub2 = (const float*)d_in[17];
    const float* row1 = (const float*)d_in[18];
    const float* rob1 = (const float*)d_in[19];
    const float* row2 = (const float*)d_in[20];
    const float* rob2 = (const float*)d_in[21];
    float* out = (float*)d_out;

    cudaFuncSetAttribute(k_upd, cudaFuncAttributeMaxDynamicSharedMemorySize, SMEM_UPD);

    k_build<<<TABM + TABRO, 64>>>(pw1, pb1, pw2, pb2, row1, rob1);
    k_init<<<N_ATOMS, 64>>>(at, emb, w1);
    for (int l = 0; l < 3; l++){
        k_msg<<<dim3(48, NSPLIT), 256>>>(dist, l);
        k_upd<<<192, 256, SMEM_UPD>>>(l, (l==2) ? 1 : 0, qw1, qb1, qw2, qb2, w1,
                                      auw1, aub1, auw2, aub2);
    }
    k_readout<<<1184, 256>>>(dist, row1, row2, rob2, out);
}

// round 6
// speedup vs baseline: 1.5817x; 1.3356x over previous
#include <cuda_runtime.h>
#include <cuda_fp16.h>
#include <math.h>

#define N_ATOMS 768
#define NM1 767
#define NEDGE (768*767)
#define DIM 64
#define NC 50
#define TABM 768
#define TABRO 512
#define CUTF 5.0f
#define GAPF (5.0f/49.0f)
#define INVH ((float)(TABM-1)/CUTF)
#define INVHRO ((float)(TABRO-1)/CUTF)
#define LN2F 0.69314718055994531f

#define NSPLIT 12
#define IPB (N_ATOMS/NSPLIT)     // 64 i-rows per block
#define JPB 16                   // 16 dst per block

#define SMEM_UPD ((3*4096 + 3*256 + 64)*4)   // 3 weight mats + sa/st/sh + au2 = 52480 B

// ---- scratch (static device allocations; no runtime alloc) ----
__device__ float g_h[N_ATOMS*DIM];
__device__ float g_nw[N_ATOMS*DIM];
__device__ float g_aggp[NSPLIT][N_ATOMS*DIM];        // per-i-split partial aggregates
__device__ float g_ha[N_ATOMS];
__device__ __align__(256) __half g_tabh[3][TABM*DIM]; // fp16 e_l(d) tables (96KB/layer)
__device__ float g_tabro[TABRO*DIM];                  // fp32 readout table (128KB)

__device__ __forceinline__ float sp05(float x){   // Softplus(beta=0.5, thr=14)
    float bx = 0.5f*x;
    return bx > 14.0f ? x : 2.0f*log1pf(expf(bx));
}
__device__ __forceinline__ float sp1(float x){    // Softplus(beta=1, thr=20)
    return x > 20.0f ? x : log1pf(expf(x));
}

// ---- build layer interpolation tables (fp16) ----
__global__ void k_build_tab(const float* __restrict__ pw1, const float* __restrict__ pb1,
                            const float* __restrict__ pw2, const float* __restrict__ pb2){
    int b = blockIdx.x, c = threadIdx.x;
    __shared__ float rbf[NC], sp[DIM];
    float d = (float)b * (CUTF/(float)(TABM-1));
    if (c < NC){ float t = d - (float)c*GAPF; rbf[c] = expf(-t*t*(1.0f/GAPF)); }
    __syncthreads();
    for (int l=0;l<3;l++){
        float u = pb1[l*DIM+c];
        #pragma unroll 10
        for (int k=0;k<NC;k++) u = fmaf(rbf[k], pw1[(l*NC+k)*DIM+c], u);
        float s = sp05(u);
        sp[c] = s; __syncthreads();
        float e = pb2[l*DIM+c];
        #pragma unroll 8
        for (int k=0;k<DIM;k++) e = fmaf(sp[k], pw2[(l*DIM+k)*DIM+c], e);
        g_tabh[l][b*DIM+c] = __float2half(e);
        __syncthreads();
    }
}

// ---- build readout table (fp32) ----
__global__ void k_build_ro(const float* __restrict__ row1, const float* __restrict__ rob1){
    int m = blockIdx.x, c = threadIdx.x;
    __shared__ float rbf[NC];
    float d = (float)m * (CUTF/(float)(TABRO-1));
    if (c < NC){ float t = d - (float)c*GAPF; rbf[c] = expf(-t*t*(1.0f/GAPF)); }
    __syncthreads();
    float v = rob1[c];
    #pragma unroll 10
    for (int k=0;k<NC;k++) v = fmaf(rbf[k], row1[(2+k)*DIM+c], v);
    g_tabro[m*DIM+c] = v;
}

// ---- h = embedding[atom_types]; nw = h @ w1[0] ----
__global__ void k_init(const int* __restrict__ at, const float* __restrict__ emb,
                       const float* __restrict__ w1){
    int n = blockIdx.x, c = threadIdx.x;
    __shared__ float sh[DIM];
    float hv = emb[at[n]*DIM + c];
    sh[c] = hv; g_h[n*DIM+c] = hv;
    __syncthreads();
    float a = 0.f;
    #pragma unroll 8
    for (int k=0;k<DIM;k++) a = fmaf(sh[k], w1[k*DIM+c], a);
    g_nw[n*DIM+c] = a;
}

// ---- message pass: aggp[isp][j] = sum_{i in split, i != j} nw[i] * lerp(tabh_l, d_ij)
// grid (48, NSPLIT). nw+dist chunk in smem; fp16 table via L1 (96KB, resident).
__global__ void __launch_bounds__(256,4) k_msg(const float* __restrict__ dist, int l){
    __shared__ float4 nw_s[IPB*16];     // 16 KB
    __shared__ float  dist_s[IPB*JPB];  // 4 KB

    int tid  = threadIdx.x;
    int grp  = tid >> 4;         // j within tile
    int g    = tid & 15;         // float4 lane
    int jbase = blockIdx.x * JPB;
    int ibase = blockIdx.y * IPB;
    int j     = jbase + grp;

    // stage nw chunk: fully coalesced, register-batched for MLP
    {
        const float4* __restrict__ nwg = (const float4*)g_nw + ibase*16;
        float4 rn[4];
        #pragma unroll
        for (int q=0;q<4;q++) rn[q] = __ldg(nwg + tid + 256*q);
        #pragma unroll
        for (int q=0;q<4;q++) nw_s[tid + 256*q] = rn[q];
    }
    // stage dist chunk: IPB i x 16 j
    {
        float rd[4];
        #pragma unroll
        for (int q=0;q<4;q++){
            int s = tid + 256*q;
            int il = s >> 4, jj = s & 15;
            int i = ibase + il, jd = jbase + jj;
            rd[q] = (i != jd) ? __ldg(dist + i*NM1 + jd - (jd > i)) : 0.f;
        }
        #pragma unroll
        for (int q=0;q<4;q++) dist_s[tid + 256*q] = rd[q];
    }
    __syncthreads();

    const __half* __restrict__ tl = g_tabh[l];
    float4 acc = make_float4(0.f,0.f,0.f,0.f);
    #pragma unroll 4
    for (int il = 0; il < IPB; il++){
        int i = ibase + il;
        if (i == j) continue;
        float x = dist_s[il*16 + grp] * INVH;
        int t = min((int)x, TABM-2);
        float f = x - (float)t;
        // row t: 64 halves = 128B; lane g covers halves [4g,4g+4) = one uint2
        const uint2* p = (const uint2*)(tl + (t << 6)) + g;
        uint2 a0 = __ldg(p);
        uint2 a1 = __ldg(p + 16);          // next row (+128B)
        float2 u0 = __half22float2(*reinterpret_cast<const __half2*>(&a0.x));
        float2 u1 = __half22float2(*reinterpret_cast<const __half2*>(&a0.y));
        float2 v0 = __half22float2(*reinterpret_cast<const __half2*>(&a1.x));
        float2 v1 = __half22float2(*reinterpret_cast<const __half2*>(&a1.y));
        float4 w  = nw_s[il*16 + g];
        acc.x = fmaf(w.x, fmaf(f, v0.x - u0.x, u0.x), acc.x);
        acc.y = fmaf(w.y, fmaf(f, v0.y - u0.y, u0.y), acc.y);
        acc.z = fmaf(w.z, fmaf(f, v1.x - u1.x, u1.x), acc.z);
        acc.w = fmaf(w.w, fmaf(f, v1.y - u1.y, u1.y), acc.w);
    }
    ((float4*)g_aggp[blockIdx.y])[j*16 + g] = acc;
}

// ---- node update: h += MLP(sum of agg partials); then nw for next layer, or ha ----
__global__ void __launch_bounds__(256) k_upd(int l, int last,
        const float* __restrict__ qw1, const float* __restrict__ qb1,
        const float* __restrict__ qw2, const float* __restrict__ qb2,
        const float* __restrict__ w1,
        const float* __restrict__ auw1, const float* __restrict__ aub1,
        const float* __restrict__ auw2, const float* __restrict__ aub2){
    extern __shared__ float sm[];
    float* wA  = sm;            // qw1[l]           (4096)
    float* wB  = sm + 4096;     // qw2[l]           (4096)
    float* wC  = sm + 8192;     // w1[l+1] or au_w1 (4096)
    float* sa  = sm + 12288;    // 4 x 64
    float* st  = sm + 12544;    // 4 x 64
    float* sh  = sm + 12800;    // 4 x 64
    float* au2 = sm + 13056;    // 64

    int tid = threadIdx.x;
    int nd  = tid >> 6;
    int c   = tid & 63;
    int n   = blockIdx.x*4 + nd;

    // register-batched staging (MLP = 12)
    {
        const float4* A4 = (const float4*)(qw1 + l*DIM*DIM);
        const float4* B4 = (const float4*)(qw2 + l*DIM*DIM);
        const float4* C4 = (const float4*)(last ? auw1 : (w1 + (l+1)*DIM*DIM));
        float4 ra[4], rb[4], rc[4];
        #pragma unroll
        for (int q=0;q<4;q++){
            ra[q] = __ldg(A4 + tid + 256*q);
            rb[q] = __ldg(B4 + tid + 256*q);
            rc[q] = __ldg(C4 + tid + 256*q);
        }
        #pragma unroll
        for (int q=0;q<4;q++){
            ((float4*)wA)[tid + 256*q] = ra[q];
            ((float4*)wB)[tid + 256*q] = rb[q];
            ((float4*)wC)[tid + 256*q] = rc[q];
        }
    }
    if (last && tid < DIM) au2[tid] = auw2[tid];

    int off = n*DIM + c;
    float a = 0.f;
    #pragma unroll
    for (int s = 0; s < NSPLIT; s++) a += g_aggp[s][off];
    sa[nd*DIM + c] = a;
    __syncthreads();

    float u = qb1[l*DIM+c];
    #pragma unroll 8
    for (int k=0;k<DIM;k++) u = fmaf(sa[nd*DIM+k], wA[k*DIM+c], u);
    st[nd*DIM + c] = sp05(u);
    __syncthreads();

    float up = qb2[l*DIM+c];
    #pragma unroll 8
    for (int k=0;k<DIM;k++) up = fmaf(st[nd*DIM+k], wB[k*DIM+c], up);
    float hn = g_h[off] + up;
    g_h[off] = hn;
    sh[nd*DIM + c] = hn;
    __syncthreads();

    if (!last){
        float a2 = 0.f;
        #pragma unroll 8
        for (int k=0;k<DIM;k++) a2 = fmaf(sh[nd*DIM+k], wC[k*DIM+c], a2);
        g_nw[off] = a2;
    } else {
        float u2 = aub1[c];
        #pragma unroll 8
        for (int k=0;k<DIM;k++) u2 = fmaf(sh[nd*DIM+k], wC[k*DIM+c], u2);
        st[nd*DIM + c] = sp1(u2) - LN2F;
        __syncthreads();
        if (c == 0){
            float acc2 = aub2[0];
            #pragma unroll 8
            for (int k=0;k<DIM;k++) acc2 = fmaf(st[nd*DIM+k], au2[k], acc2);
            g_ha[n] = acc2;
        }
    }
}

// ---- readout: softmax(relu([ha_i, ha_j, rbf] @ ro_w1 + b1) @ ro_w2 + b2) per edge
__global__ void __launch_bounds__(256) k_readout(const float* __restrict__ dist,
        const float* __restrict__ row1, const float* __restrict__ row2,
        const float* __restrict__ rob2, float* __restrict__ out){
    int g = threadIdx.x & 15;
    float4 wa  = __ldg((const float4*)row1 + g);          // ro_w1 row 0 (ha_src)
    float4 wb  = __ldg((const float4*)(row1 + DIM) + g);  // ro_w1 row 1 (ha_dst)
    float4 w2a = __ldg((const float4*)row2 + 2*g);
    float4 w2b = __ldg((const float4*)row2 + 2*g + 1);
    float b20 = rob2[0], b21 = rob2[1];
    int group   = (blockIdx.x * blockDim.x + threadIdx.x) >> 4;
    int ngroups = (gridDim.x * blockDim.x) >> 4;
    for (int e = group; e < NEDGE; e += ngroups){
        int i = e / NM1;
        int r = e - i*NM1;
        int j = r + (r >= i);
        float d = __ldg(dist + e);
        float x = d * INVHRO;
        int t = min((int)x, TABRO-2);
        float f = x - (float)t;
        const float4* rp = (const float4*)g_tabro + t*16;
        float4 t0 = __ldg(rp + g);
        float4 t1 = __ldg(rp + 16 + g);
        float hi = g_ha[i];
        float hj = g_ha[j];
        float z0 = fmaf(f, t1.x-t0.x, t0.x) + hi*wa.x + hj*wb.x; z0 = fmaxf(z0, 0.f);
        float z1 = fmaf(f, t1.y-t0.y, t0.y) + hi*wa.y + hj*wb.y; z1 = fmaxf(z1, 0.f);
        float z2 = fmaf(f, t1.z-t0.z, t0.z) + hi*wa.z + hj*wb.z; z2 = fmaxf(z2, 0.f);
        float z3 = fmaf(f, t1.w-t0.w, t0.w) + hi*wa.w + hj*wb.w; z3 = fmaxf(z3, 0.f);
        float a0 = z0*w2a.x + z1*w2a.z + z2*w2b.x + z3*w2b.z;
        float a1 = z0*w2a.y + z1*w2a.w + z2*w2b.y + z3*w2b.w;
        #pragma unroll
        for (int off=8; off; off>>=1){
            a0 += __shfl_xor_sync(0xffffffffu, a0, off);
            a1 += __shfl_xor_sync(0xffffffffu, a1, off);
        }
        if (g == 0){
            float l0 = a0 + b20, l1 = a1 + b21;
            float m = fmaxf(l0, l1);
            float e0 = __expf(l0 - m), e1 = __expf(l1 - m);
            float inv = 1.0f/(e0 + e1);
            ((float2*)out)[e] = make_float2(e0*inv, e1*inv);
        }
    }
}

extern "C" void kernel_launch(void* const* d_in, const int* in_sizes, int n_in,
                              void* d_out, int out_size){
    const int*   at   = (const int*)  d_in[0];
    const float* dist = (const float*)d_in[1];
    // d_in[2]=src, d_in[3]=dst (recomputed analytically; complete graph)
    const float* emb  = (const float*)d_in[4];
    const float* w1   = (const float*)d_in[5];
    const float* pw1  = (const float*)d_in[6];
    const float* pb1  = (const float*)d_in[7];
    const float* pw2  = (const float*)d_in[8];
    const float* pb2  = (const float*)d_in[9];
    const float* qw1  = (const float*)d_in[10];
    const float* qb1  = (const float*)d_in[11];
    const float* qw2  = (const float*)d_in[12];
    const float* qb2  = (const float*)d_in[13];
    const float* auw1 = (const float*)d_in[14];
    const float* aub1 = (const float*)d_in[15];
    const float* auw2 = (const float*)d_in[16];
    const float* aub2 = (const float*)d_in[17];
    const float* row1 = (const float*)d_in[18];
    const float* rob1 = (const float*)d_in[19];
    const float* row2 = (const float*)d_in[20];
    const float* rob2 = (const float*)d_in[21];
    float* out = (float*)d_out;

    cudaFuncSetAttribute(k_upd, cudaFuncAttributeMaxDynamicSharedMemorySize, SMEM_UPD);

    // launch order chosen so ncu's fixed "-s 5 -c 1" captures k_msg(l=1):
    // 0:build_tab 1:build_ro 2:init 3:msg 4:upd 5:msg <- profiled
    k_build_tab<<<TABM, 64>>>(pw1, pb1, pw2, pb2);
    k_build_ro<<<TABRO, 64>>>(row1, rob1);
    k_init<<<N_ATOMS, 64>>>(at, emb, w1);
    for (int l = 0; l < 3; l++){
        k_msg<<<dim3(48, NSPLIT), 256>>>(dist, l);
        k_upd<<<192, 256, SMEM_UPD>>>(l, (l==2) ? 1 : 0, qw1, qb1, qw2, qb2, w1,
                                      auw1, aub1, auw2, aub2);
    }
    k_readout<<<1184, 256>>>(dist, row1, row2, rob2, out);
}

// round 8
// speedup vs baseline: 1.8085x; 1.1434x over previous
#include <cuda_runtime.h>
#include <cuda_fp16.h>
#include <math.h>

#define N_ATOMS 768
#define NM1 767
#define NEDGE (768*767)
#define DIM 64
#define NC 50
#define TABM 768
#define TABRO 512
#define CUTF 5.0f
#define GAPF (5.0f/49.0f)
#define INVH ((float)(TABM-1)/CUTF)
#define INVHRO ((float)(TABRO-1)/CUTF)
#define LN2F 0.69314718055994531f

#define NSPLIT 12
#define IPB (N_ATOMS/NSPLIT)     // 64 i-rows per block
#define JPB 16                   // 16 dst per block

#define SMEM_UPD ((3*4096 + 3*256 + 64)*4)   // 52480 B

// ---- scratch (static device allocations; no runtime alloc) ----
__device__ float g_h[N_ATOMS*DIM];
__device__ float g_nw[N_ATOMS*DIM];
__device__ float g_aggp[NSPLIT][N_ATOMS*DIM];        // per-i-split partial aggregates
__device__ float g_ha[N_ATOMS];
__device__ __align__(256) __half g_tabh[3][TABM*DIM]; // fp16 e_l(d) tables (96KB/layer)
__device__ float g_tabro[TABRO*DIM];                  // fp32 readout table (128KB)

__device__ __forceinline__ float sp05(float x){   // Softplus(beta=0.5, thr=14)
    float bx = 0.5f*x;
    return bx > 14.0f ? x : 2.0f*log1pf(expf(bx));
}
__device__ __forceinline__ float sp1(float x){    // Softplus(beta=1, thr=20)
    return x > 20.0f ? x : log1pf(expf(x));
}

// ---- fused preamble: layer tables (fp16) + readout table (fp32) + h/nw init ----
// blocks [0,768): tab ; [768,1280): ro ; [1280,2048): init
__global__ void k_pre(const float* __restrict__ pw1, const float* __restrict__ pb1,
                      const float* __restrict__ pw2, const float* __restrict__ pb2,
                      const float* __restrict__ row1, const float* __restrict__ rob1,
                      const int* __restrict__ at, const float* __restrict__ emb,
                      const float* __restrict__ w1){
    int b = blockIdx.x, c = threadIdx.x;
    __shared__ float sbuf[DIM];
    __shared__ float rbf[NC];
    if (b < TABM){
        float d = (float)b * (CUTF/(float)(TABM-1));
        if (c < NC){ float t = d - (float)c*GAPF; rbf[c] = expf(-t*t*(1.0f/GAPF)); }
        __syncthreads();
        for (int l=0;l<3;l++){
            float u = pb1[l*DIM+c];
            #pragma unroll 10
            for (int k=0;k<NC;k++) u = fmaf(rbf[k], pw1[(l*NC+k)*DIM+c], u);
            float s = sp05(u);
            sbuf[c] = s; __syncthreads();
            float e = pb2[l*DIM+c];
            #pragma unroll 8
            for (int k=0;k<DIM;k++) e = fmaf(sbuf[k], pw2[(l*DIM+k)*DIM+c], e);
            g_tabh[l][b*DIM+c] = __float2half(e);
            __syncthreads();
        }
    } else if (b < TABM + TABRO){
        int m = b - TABM;
        float d = (float)m * (CUTF/(float)(TABRO-1));
        if (c < NC){ float t = d - (float)c*GAPF; rbf[c] = expf(-t*t*(1.0f/GAPF)); }
        __syncthreads();
        float v = rob1[c];
        #pragma unroll 10
        for (int k=0;k<NC;k++) v = fmaf(rbf[k], row1[(2+k)*DIM+c], v);
        g_tabro[m*DIM+c] = v;
    } else {
        int n = b - TABM - TABRO;
        float hv = emb[at[n]*DIM + c];
        sbuf[c] = hv; g_h[n*DIM+c] = hv;
        __syncthreads();
        float a = 0.f;
        #pragma unroll 8
        for (int k=0;k<DIM;k++) a = fmaf(sbuf[k], w1[k*DIM+c], a);
        g_nw[n*DIM+c] = a;
    }
}

// ---- message pass: aggp[isp][j] = sum_{i in split, i != j} nw[i] * lerp(tabh_l, d_ij)
// (f, t*128) precomputed once per edge during staging; branchless inner loop with
// analytic i==j correction after the loop.
__global__ void __launch_bounds__(256,4) k_msg(const float* __restrict__ dist, int l){
    __shared__ float4 nw_s[IPB*16];     // 16 KB
    __shared__ float2 ed_s[IPB*JPB];    // 8 KB : {f, bitcast(t*128)}

    int tid  = threadIdx.x;
    int grp  = tid >> 4;         // j within tile
    int g    = tid & 15;         // float4 lane
    int jbase = blockIdx.x * JPB;
    int ibase = blockIdx.y * IPB;
    int j     = jbase + grp;

    // stage nw chunk: coalesced, register-batched
    {
        const float4* __restrict__ nwg = (const float4*)g_nw + ibase*16;
        float4 rn[4];
        #pragma unroll
        for (int q=0;q<4;q++) rn[q] = __ldg(nwg + tid + 256*q);
        #pragma unroll
        for (int q=0;q<4;q++) nw_s[tid + 256*q] = rn[q];
    }
    // stage per-edge (f, toff): index math done ONCE per edge here
    {
        float2 rd[4];
        #pragma unroll
        for (int q=0;q<4;q++){
            int s = tid + 256*q;
            int il = s >> 4, jj = s & 15;
            int i = ibase + il, jd = jbase + jj;
            float dv = (i != jd) ? __ldg(dist + i*NM1 + jd - (jd > i)) : 0.f;
            float x = dv * INVH;
            int t = min((int)x, TABM-2);
            rd[q] = make_float2(x - (float)t, __uint_as_float((unsigned)t * 128u));
        }
        #pragma unroll
        for (int q=0;q<4;q++) ed_s[tid + 256*q] = rd[q];
    }
    __syncthreads();

    const char* __restrict__ tp = (const char*)g_tabh[l] + g*8;
    float4 acc = make_float4(0.f,0.f,0.f,0.f);
    #pragma unroll 4
    for (int il = 0; il < IPB; il++){
        float2 ed = ed_s[il*16 + grp];
        const uint2* p = (const uint2*)(tp + __float_as_uint(ed.y));
        uint2 a0 = __ldg(p);
        uint2 a1 = __ldg(p + 16);          // next table row (+128B)
        float f  = ed.x;
        float2 u0 = __half22float2(*reinterpret_cast<const __half2*>(&a0.x));
        float2 u1 = __half22float2(*reinterpret_cast<const __half2*>(&a0.y));
        float2 v0 = __half22float2(*reinterpret_cast<const __half2*>(&a1.x));
        float2 v1 = __half22float2(*reinterpret_cast<const __half2*>(&a1.y));
        float4 w  = nw_s[il*16 + g];
        acc.x = fmaf(w.x, fmaf(f, v0.x - u0.x, u0.x), acc.x);
        acc.y = fmaf(w.y, fmaf(f, v0.y - u0.y, u0.y), acc.y);
        acc.z = fmaf(w.z, fmaf(f, v1.x - u1.x, u1.x), acc.z);
        acc.w = fmaf(w.w, fmaf(f, v1.y - u1.y, u1.y), acc.w);
    }
    // remove the i==j self-term (was computed with d=0 -> exact table row 0)
    int jl = j - ibase;
    if (jl >= 0 && jl < IPB){
        uint2 a0 = *(const uint2*)tp;    // row 0, f=0
        float2 u0 = __half22float2(*reinterpret_cast<const __half2*>(&a0.x));
        float2 u1 = __half22float2(*reinterpret_cast<const __half2*>(&a0.y));
        float4 w  = nw_s[jl*16 + g];
        acc.x -= w.x*u0.x; acc.y -= w.y*u0.y;
        acc.z -= w.z*u1.x; acc.w -= w.w*u1.y;
    }
    ((float4*)g_aggp[blockIdx.y])[j*16 + g] = acc;
}

// ---- node update: h += MLP(sum of agg partials); then nw for next layer, or ha ----
__global__ void __launch_bounds__(256) k_upd(int l, int last,
        const float* __restrict__ qw1, const float* __restrict__ qb1,
        const float* __restrict__ qw2, const float* __restrict__ qb2,
        const float* __restrict__ w1,
        const float* __restrict__ auw1, const float* __restrict__ aub1,
        const float* __restrict__ auw2, const float* __restrict__ aub2){
    extern __shared__ float sm[];
    float* wA  = sm;            // qw1[l]
    float* wB  = sm + 4096;     // qw2[l]
    float* wC  = sm + 8192;     // w1[l+1] or au_w1
    float* sa  = sm + 12288;
    float* st  = sm + 12544;
    float* sh  = sm + 12800;
    float* au2 = sm + 13056;

    int tid = threadIdx.x;
    int nd  = tid >> 6;
    int c   = tid & 63;
    int n   = blockIdx.x*4 + nd;

    {
        const float4* A4 = (const float4*)(qw1 + l*DIM*DIM);
        const float4* B4 = (const float4*)(qw2 + l*DIM*DIM);
        const float4* C4 = (const float4*)(last ? auw1 : (w1 + (l+1)*DIM*DIM));
        float4 ra[4], rb[4], rc[4];
        #pragma unroll
        for (int q=0;q<4;q++){
            ra[q] = __ldg(A4 + tid + 256*q);
            rb[q] = __ldg(B4 + tid + 256*q);
            rc[q] = __ldg(C4 + tid + 256*q);
        }
        #pragma unroll
        for (int q=0;q<4;q++){
            ((float4*)wA)[tid + 256*q] = ra[q];
            ((float4*)wB)[tid + 256*q] = rb[q];
            ((float4*)wC)[tid + 256*q] = rc[q];
        }
    }
    if (last && tid < DIM) au2[tid] = auw2[tid];

    int off = n*DIM + c;
    float a = 0.f;
    #pragma unroll
    for (int s = 0; s < NSPLIT; s++) a += g_aggp[s][off];
    sa[nd*DIM + c] = a;
    __syncthreads();

    float u = qb1[l*DIM+c];
    #pragma unroll 8
    for (int k=0;k<DIM;k++) u = fmaf(sa[nd*DIM+k], wA[k*DIM+c], u);
    st[nd*DIM + c] = sp05(u);
    __syncthreads();

    float up = qb2[l*DIM+c];
    #pragma unroll 8
    for (int k=0;k<DIM;k++) up = fmaf(st[nd*DIM+k], wB[k*DIM+c], up);
    float hn = g_h[off] + up;
    g_h[off] = hn;
    sh[nd*DIM + c] = hn;
    __syncthreads();

    if (!last){
        float a2 = 0.f;
        #pragma unroll 8
        for (int k=0;k<DIM;k++) a2 = fmaf(sh[nd*DIM+k], wC[k*DIM+c], a2);
        g_nw[off] = a2;
    } else {
        float u2 = aub1[c];
        #pragma unroll 8
        for (int k=0;k<DIM;k++) u2 = fmaf(sh[nd*DIM+k], wC[k*DIM+c], u2);
        st[nd*DIM + c] = sp1(u2) - LN2F;
        __syncthreads();
        if (c == 0){
            float acc2 = aub2[0];
            #pragma unroll 8
            for (int k=0;k<DIM;k++) acc2 = fmaf(st[nd*DIM+k], au2[k], acc2);
            g_ha[n] = acc2;
        }
    }
}

// ---- readout: i-major (one block per src atom i); no integer division ----
__global__ void __launch_bounds__(256) k_readout(const float* __restrict__ dist,
        const float* __restrict__ row1, const float* __restrict__ row2,
        const float* __restrict__ rob2, float* __restrict__ out){
    int i   = blockIdx.x;
    int grp = threadIdx.x >> 4;
    int g   = threadIdx.x & 15;
    float4 wa  = __ldg((const float4*)row1 + g);          // ro_w1 row 0 (ha_src)
    float4 wb  = __ldg((const float4*)(row1 + DIM) + g);  // ro_w1 row 1 (ha_dst)
    float4 w2a = __ldg((const float4*)row2 + 2*g);
    float4 w2b = __ldg((const float4*)row2 + 2*g + 1);
    float b20 = rob2[0], b21 = rob2[1];
    float hi = g_ha[i];
    // hoist hi * wa
    float4 base = make_float4(hi*wa.x, hi*wa.y, hi*wa.z, hi*wa.w);
    long ebase = (long)i * NM1;
    for (int r = grp; r < NM1; r += 16){
        int jd = r + (r >= i);
        long e = ebase + r;
        float d = __ldg(dist + e);
        float x = d * INVHRO;
        int t = min((int)x, TABRO-2);
        float f = x - (float)t;
        const float4* rp = (const float4*)g_tabro + t*16;
        float4 t0 = __ldg(rp + g);
        float4 t1 = __ldg(rp + 16 + g);
        float hj = __ldg(g_ha + jd);
        float z0 = fmaf(f, t1.x-t0.x, t0.x) + base.x + hj*wb.x; z0 = fmaxf(z0, 0.f);
        float z1 = fmaf(f, t1.y-t0.y, t0.y) + base.y + hj*wb.y; z1 = fmaxf(z1, 0.f);
        float z2 = fmaf(f, t1.z-t0.z, t0.z) + base.z + hj*wb.z; z2 = fmaxf(z2, 0.f);
        float z3 = fmaf(f, t1.w-t0.w, t0.w) + base.w + hj*wb.w; z3 = fmaxf(z3, 0.f);
        float a0 = z0*w2a.x + z1*w2a.z + z2*w2b.x + z3*w2b.z;
        float a1 = z0*w2a.y + z1*w2a.w + z2*w2b.y + z3*w2b.w;
        #pragma unroll
        for (int off=8; off; off>>=1){
            a0 += __shfl_xor_sync(0xffffffffu, a0, off);
            a1 += __shfl_xor_sync(0xffffffffu, a1, off);
        }
        if (g == 0){
            float l0 = a0 + b20, l1 = a1 + b21;
            float m = fmaxf(l0, l1);
            float e0 = __expf(l0 - m), e1 = __expf(l1 - m);
            float inv = 1.0f/(e0 + e1);
            ((float2*)out)[e] = make_float2(e0*inv, e1*inv);
        }
    }
}

extern "C" void kernel_launch(void* const* d_in, const int* in_sizes, int n_in,
                              void* d_out, int out_size){
    const int*   at   = (const int*)  d_in[0];
    const float* dist = (const float*)d_in[1];
    // d_in[2]=src, d_in[3]=dst (recomputed analytically; complete graph)
    const float* emb  = (const float*)d_in[4];
    const float* w1   = (const float*)d_in[5];
    const float* pw1  = (const float*)d_in[6];
    const float* pb1  = (const float*)d_in[7];
    const float* pw2  = (const float*)d_in[8];
    const float* pb2  = (const float*)d_in[9];
    const float* qw1  = (const float*)d_in[10];
    const float* qb1  = (const float*)d_in[11];
    const float* qw2  = (const float*)d_in[12];
    const float* qb2  = (const float*)d_in[13];
    const float* auw1 = (const float*)d_in[14];
    const float* aub1 = (const float*)d_in[15];
    const float* auw2 = (const float*)d_in[16];
    const float* aub2 = (const float*)d_in[17];
    const float* row1 = (const float*)d_in[18];
    const float* rob1 = (const float*)d_in[19];
    const float* row2 = (const float*)d_in[20];
    const float* rob2 = (const float*)d_in[21];
    float* out = (float*)d_out;

    cudaFuncSetAttribute(k_upd, cudaFuncAttributeMaxDynamicSharedMemorySize, SMEM_UPD);

    // launch index for ncu -s 5: 0:pre 1:msg 2:upd 3:msg 4:upd 5:msg <- profiled
    k_pre<<<TABM + TABRO + N_ATOMS, 64>>>(pw1, pb1, pw2, pb2, row1, rob1, at, emb, w1);
    for (int l = 0; l < 3; l++){
        k_msg<<<dim3(48, NSPLIT), 256>>>(dist, l);
        k_upd<<<192, 256, SMEM_UPD>>>(l, (l==2) ? 1 : 0, qw1, qb1, qw2, qb2, w1,
                                      auw1, aub1, auw2, aub2);
    }
    k_readout<<<N_ATOMS, 256>>>(dist, row1, row2, rob2, out);
}

// round 9
// speedup vs baseline: 1.9016x; 1.0514x over previous
#include <cuda_runtime.h>
#include <cuda_fp16.h>
#include <math.h>

#define N_ATOMS 768
#define NM1 767
#define NEDGE (768*767)
#define DIM 64
#define NC 50
#define TABM 768
#define TABRO 512
#define CUTF 5.0f
#define GAPF (5.0f/49.0f)
#define INVH ((float)(TABM-1)/CUTF)
#define INVHRO ((float)(TABRO-1)/CUTF)
#define LN2F 0.69314718055994531f

#define NSPLIT 12
#define IPB (N_ATOMS/NSPLIT)     // 64 i-rows per block
#define JPB 16                   // 16 dst per block

#define SMEM_UPD ((3*4096 + 3*256 + 64)*4)   // 52480 B

// ---- scratch (static device allocations; no runtime alloc) ----
__device__ float g_h[N_ATOMS*DIM];
__device__ float g_nw[N_ATOMS*DIM];
__device__ float g_aggp[NSPLIT][N_ATOMS*DIM];        // per-i-split partial aggregates
__device__ float g_ha[N_ATOMS];
__device__ __align__(256) __half g_tabh[3][TABM*DIM]; // fp16 e_l(d) tables (96KB/layer)
__device__ float g_tabro[TABRO*DIM];                  // fp32 readout table (128KB)

__device__ __forceinline__ float sp05(float x){   // Softplus(beta=0.5, thr=14)
    float bx = 0.5f*x;
    return bx > 14.0f ? x : 2.0f*log1pf(expf(bx));
}
__device__ __forceinline__ float sp1(float x){    // Softplus(beta=1, thr=20)
    return x > 20.0f ? x : log1pf(expf(x));
}

// ---- fused preamble: layer tables (fp16) + readout table (fp32) + h/nw init ----
__global__ void k_pre(const float* __restrict__ pw1, const float* __restrict__ pb1,
                      const float* __restrict__ pw2, const float* __restrict__ pb2,
                      const float* __restrict__ row1, const float* __restrict__ rob1,
                      const int* __restrict__ at, const float* __restrict__ emb,
                      const float* __restrict__ w1){
    int b = blockIdx.x, c = threadIdx.x;
    __shared__ float sbuf[DIM];
    __shared__ float rbf[NC];
    if (b < TABM){
        float d = (float)b * (CUTF/(float)(TABM-1));
        if (c < NC){ float t = d - (float)c*GAPF; rbf[c] = expf(-t*t*(1.0f/GAPF)); }
        __syncthreads();
        for (int l=0;l<3;l++){
            float u0 = pb1[l*DIM+c], u1 = 0.f;
            #pragma unroll 10
            for (int k=0;k<NC-1;k+=2){
                u0 = fmaf(rbf[k],   pw1[(l*NC+k)*DIM+c],   u0);
                u1 = fmaf(rbf[k+1], pw1[(l*NC+k+1)*DIM+c], u1);
            }
            u0 = fmaf(rbf[NC-1], pw1[(l*NC+NC-1)*DIM+c], u0);
            float s = sp05(u0 + u1);
            sbuf[c] = s; __syncthreads();
            float e0 = pb2[l*DIM+c], e1 = 0.f;
            #pragma unroll 8
            for (int k=0;k<DIM;k+=2){
                e0 = fmaf(sbuf[k],   pw2[(l*DIM+k)*DIM+c],   e0);
                e1 = fmaf(sbuf[k+1], pw2[(l*DIM+k+1)*DIM+c], e1);
            }
            g_tabh[l][b*DIM+c] = __float2half(e0 + e1);
            __syncthreads();
        }
    } else if (b < TABM + TABRO){
        int m = b - TABM;
        float d = (float)m * (CUTF/(float)(TABRO-1));
        if (c < NC){ float t = d - (float)c*GAPF; rbf[c] = expf(-t*t*(1.0f/GAPF)); }
        __syncthreads();
        float v0 = rob1[c], v1 = 0.f;
        #pragma unroll 10
        for (int k=0;k<NC-1;k+=2){
            v0 = fmaf(rbf[k],   row1[(2+k)*DIM+c],   v0);
            v1 = fmaf(rbf[k+1], row1[(2+k+1)*DIM+c], v1);
        }
        v0 = fmaf(rbf[NC-1], row1[(2+NC-1)*DIM+c], v0);
        g_tabro[m*DIM+c] = v0 + v1;
    } else {
        int n = b - TABM - TABRO;
        float hv = emb[at[n]*DIM + c];
        sbuf[c] = hv; g_h[n*DIM+c] = hv;
        __syncthreads();
        float a0 = 0.f, a1 = 0.f;
        #pragma unroll 8
        for (int k=0;k<DIM;k+=2){
            a0 = fmaf(sbuf[k],   w1[k*DIM+c],     a0);
            a1 = fmaf(sbuf[k+1], w1[(k+1)*DIM+c], a1);
        }
        g_nw[n*DIM+c] = a0 + a1;
    }
}

// ---- message pass: aggp[isp][j] = sum_{i in split, i != j} nw[i] * lerp(tabh_l, d_ij)
// (f as half2, t*128) precomputed per edge; branchless half2 HFMA2 lerp inner loop;
// analytic i==j correction after the loop (f=0 lerp is exact in half).
__global__ void __launch_bounds__(256,6) k_msg(const float* __restrict__ dist, int l){
    __shared__ float4 nw_s[IPB*16];     // 16 KB
    __shared__ uint2  ed_s[IPB*JPB];    // 8 KB : {f packed half2, t*128}

    int tid  = threadIdx.x;
    int grp  = tid >> 4;         // j within tile
    int g    = tid & 15;         // float4 lane
    int jbase = blockIdx.x * JPB;
    int ibase = blockIdx.y * IPB;
    int j     = jbase + grp;

    // stage nw chunk: coalesced, register-batched
    {
        const float4* __restrict__ nwg = (const float4*)g_nw + ibase*16;
        float4 rn[4];
        #pragma unroll
        for (int q=0;q<4;q++) rn[q] = __ldg(nwg + tid + 256*q);
        #pragma unroll
        for (int q=0;q<4;q++) nw_s[tid + 256*q] = rn[q];
    }
    // stage per-edge (f half2, toff): index math done ONCE per edge here
    {
        uint2 rd[4];
        #pragma unroll
        for (int q=0;q<4;q++){
            int s = tid + 256*q;
            int il = s >> 4, jj = s & 15;
            int i = ibase + il, jd = jbase + jj;
            float dv = (i != jd) ? __ldg(dist + i*NM1 + jd - (jd > i)) : 0.f;
            float x = dv * INVH;
            int t = min((int)x, TABM-2);
            __half2 f2 = __float2half2_rn(x - (float)t);
            rd[q] = make_uint2(*reinterpret_cast<unsigned*>(&f2), (unsigned)t * 128u);
        }
        #pragma unroll
        for (int q=0;q<4;q++) ed_s[tid + 256*q] = rd[q];
    }
    __syncthreads();

    const char* __restrict__ tp = (const char*)g_tabh[l] + g*8;
    float4 acc = make_float4(0.f,0.f,0.f,0.f);
    #pragma unroll 4
    for (int il = 0; il < IPB; il++){
        uint2 ed = ed_s[il*16 + grp];
        const uint2* p = (const uint2*)(tp + ed.y);
        uint2 a0 = __ldg(p);
        uint2 a1 = __ldg(p + 16);          // next table row (+128B)
        __half2 f2 = *reinterpret_cast<__half2*>(&ed.x);
        __half2 lo0 = *reinterpret_cast<__half2*>(&a0.x);
        __half2 lo1 = *reinterpret_cast<__half2*>(&a0.y);
        __half2 hi0 = *reinterpret_cast<__half2*>(&a1.x);
        __half2 hi1 = *reinterpret_cast<__half2*>(&a1.y);
        __half2 r0 = __hfma2(f2, __hsub2(hi0, lo0), lo0);
        __half2 r1 = __hfma2(f2, __hsub2(hi1, lo1), lo1);
        float4 w = nw_s[il*16 + g];
        acc.x = fmaf(w.x, __low2float(r0),  acc.x);
        acc.y = fmaf(w.y, __high2float(r0), acc.y);
        acc.z = fmaf(w.z, __low2float(r1),  acc.z);
        acc.w = fmaf(w.w, __high2float(r1), acc.w);
    }
    // remove the i==j self-term (computed with d=0 -> exact table row 0)
    int jl = j - ibase;
    if (jl >= 0 && jl < IPB){
        uint2 a0 = *(const uint2*)tp;    // row 0
        float2 u0 = __half22float2(*reinterpret_cast<const __half2*>(&a0.x));
        float2 u1 = __half22float2(*reinterpret_cast<const __half2*>(&a0.y));
        float4 w  = nw_s[jl*16 + g];
        acc.x -= w.x*u0.x; acc.y -= w.y*u0.y;
        acc.z -= w.z*u1.x; acc.w -= w.w*u1.y;
    }
    ((float4*)g_aggp[blockIdx.y])[j*16 + g] = acc;
}

// ---- node update: h += MLP(sum of agg partials); then nw for next layer, or ha ----
// 4-way split accumulators break the serial FMA dependency chains.
__global__ void __launch_bounds__(256) k_upd(int l, int last,
        const float* __restrict__ qw1, const float* __restrict__ qb1,
        const float* __restrict__ qw2, const float* __restrict__ qb2,
        const float* __restrict__ w1,
        const float* __restrict__ auw1, const float* __restrict__ aub1,
        const float* __restrict__ auw2, const float* __restrict__ aub2){
    extern __shared__ float sm[];
    float* wA  = sm;            // qw1[l]
    float* wB  = sm + 4096;     // qw2[l]
    float* wC  = sm + 8192;     // w1[l+1] or au_w1
    float* sa  = sm + 12288;
    float* st  = sm + 12544;
    float* sh  = sm + 12800;
    float* au2 = sm + 13056;

    int tid = threadIdx.x;
    int nd  = tid >> 6;
    int c   = tid & 63;
    int n   = blockIdx.x*4 + nd;

    {
        const float4* A4 = (const float4*)(qw1 + l*DIM*DIM);
        const float4* B4 = (const float4*)(qw2 + l*DIM*DIM);
        const float4* C4 = (const float4*)(last ? auw1 : (w1 + (l+1)*DIM*DIM));
        float4 ra[4], rb[4], rc[4];
        #pragma unroll
        for (int q=0;q<4;q++){
            ra[q] = __ldg(A4 + tid + 256*q);
            rb[q] = __ldg(B4 + tid + 256*q);
            rc[q] = __ldg(C4 + tid + 256*q);
        }
        #pragma unroll
        for (int q=0;q<4;q++){
            ((float4*)wA)[tid + 256*q] = ra[q];
            ((float4*)wB)[tid + 256*q] = rb[q];
            ((float4*)wC)[tid + 256*q] = rc[q];
        }
    }
    if (last && tid < DIM) au2[tid] = auw2[tid];

    int off = n*DIM + c;
    float a = 0.f;
    #pragma unroll
    for (int s = 0; s < NSPLIT; s++) a += g_aggp[s][off];
    sa[nd*DIM + c] = a;
    __syncthreads();

    float u0 = qb1[l*DIM+c], u1 = 0.f, u2 = 0.f, u3 = 0.f;
    #pragma unroll 4
    for (int k=0;k<DIM;k+=4){
        u0 = fmaf(sa[nd*DIM+k],   wA[k*DIM+c],     u0);
        u1 = fmaf(sa[nd*DIM+k+1], wA[(k+1)*DIM+c], u1);
        u2 = fmaf(sa[nd*DIM+k+2], wA[(k+2)*DIM+c], u2);
        u3 = fmaf(sa[nd*DIM+k+3], wA[(k+3)*DIM+c], u3);
    }
    st[nd*DIM + c] = sp05((u0+u1)+(u2+u3));
    __syncthreads();

    float p0 = qb2[l*DIM+c], p1 = 0.f, p2 = 0.f, p3 = 0.f;
    #pragma unroll 4
    for (int k=0;k<DIM;k+=4){
        p0 = fmaf(st[nd*DIM+k],   wB[k*DIM+c],     p0);
        p1 = fmaf(st[nd*DIM+k+1], wB[(k+1)*DIM+c], p1);
        p2 = fmaf(st[nd*DIM+k+2], wB[(k+2)*DIM+c], p2);
        p3 = fmaf(st[nd*DIM+k+3], wB[(k+3)*DIM+c], p3);
    }
    float hn = g_h[off] + ((p0+p1)+(p2+p3));
    g_h[off] = hn;
    sh[nd*DIM + c] = hn;
    __syncthreads();

    if (!last){
        float a0 = 0.f, a1 = 0.f, a2 = 0.f, a3 = 0.f;
        #pragma unroll 4
        for (int k=0;k<DIM;k+=4){
            a0 = fmaf(sh[nd*DIM+k],   wC[k*DIM+c],     a0);
            a1 = fmaf(sh[nd*DIM+k+1], wC[(k+1)*DIM+c], a1);
            a2 = fmaf(sh[nd*DIM+k+2], wC[(k+2)*DIM+c], a2);
            a3 = fmaf(sh[nd*DIM+k+3], wC[(k+3)*DIM+c], a3);
        }
        g_nw[off] = (a0+a1)+(a2+a3);
    } else {
        float a0 = aub1[c], a1 = 0.f, a2 = 0.f, a3 = 0.f;
        #pragma unroll 4
        for (int k=0;k<DIM;k+=4){
            a0 = fmaf(sh[nd*DIM+k],   wC[k*DIM+c],     a0);
            a1 = fmaf(sh[nd*DIM+k+1], wC[(k+1)*DIM+c], a1);
            a2 = fmaf(sh[nd*DIM+k+2], wC[(k+2)*DIM+c], a2);
            a3 = fmaf(sh[nd*DIM+k+3], wC[(k+3)*DIM+c], a3);
        }
        st[nd*DIM + c] = sp1((a0+a1)+(a2+a3)) - LN2F;
        __syncthreads();
        if (c == 0){
            float acc2 = aub2[0];
            #pragma unroll 8
            for (int k=0;k<DIM;k++) acc2 = fmaf(st[nd*DIM+k], au2[k], acc2);
            g_ha[n] = acc2;
        }
    }
}

// ---- readout: i-major; per-edge scalars (f, toff, hj) staged once in smem ----
__global__ void __launch_bounds__(256) k_readout(const float* __restrict__ dist,
        const float* __restrict__ row1, const float* __restrict__ row2,
        const float* __restrict__ rob2, float* __restrict__ out){
    __shared__ float4 ed_s[NM1 + 1];
    int i   = blockIdx.x;
    int tid = threadIdx.x;
    int grp = tid >> 4;
    int g   = tid & 15;
    long ebase = (long)i * NM1;

    // stage per-edge scalars: f, byte-offset into tabro, hj
    for (int r = tid; r < NM1; r += 256){
        int jd = r + (r >= i);
        float d = __ldg(dist + ebase + r);
        float x = d * INVHRO;
        int t = min((int)x, TABRO-2);
        float hj = __ldg(g_ha + jd);
        ed_s[r] = make_float4(x - (float)t, __uint_as_float((unsigned)t * 256u), hj, 0.f);
    }

    float4 wa  = __ldg((const float4*)row1 + g);          // ro_w1 row 0 (ha_src)
    float4 wb  = __ldg((const float4*)(row1 + DIM) + g);  // ro_w1 row 1 (ha_dst)
    float4 w2a = __ldg((const float4*)row2 + 2*g);
    float4 w2b = __ldg((const float4*)row2 + 2*g + 1);
    float b20 = rob2[0], b21 = rob2[1];
    float hi = __ldg(g_ha + i);
    float4 base = make_float4(hi*wa.x, hi*wa.y, hi*wa.z, hi*wa.w);
    const char* tp = (const char*)g_tabro + g*16;
    __syncthreads();

    for (int r = grp; r < NM1; r += 16){
        float4 ed = ed_s[r];
        const float4* p = (const float4*)(tp + __float_as_uint(ed.y));
        float4 t0 = __ldg(p);
        float4 t1 = __ldg(p + 16);       // next row (+256B)
        float f = ed.x, hj = ed.z;
        float z0 = fmaxf(fmaf(hj, wb.x, fmaf(f, t1.x-t0.x, t0.x) + base.x), 0.f);
        float z1 = fmaxf(fmaf(hj, wb.y, fmaf(f, t1.y-t0.y, t0.y) + base.y), 0.f);
        float z2 = fmaxf(fmaf(hj, wb.z, fmaf(f, t1.z-t0.z, t0.z) + base.z), 0.f);
        float z3 = fmaxf(fmaf(hj, wb.w, fmaf(f, t1.w-t0.w, t0.w) + base.w), 0.f);
        float a0 = z0*w2a.x + z1*w2a.z + z2*w2b.x + z3*w2b.z;
        float a1 = z0*w2a.y + z1*w2a.w + z2*w2b.y + z3*w2b.w;
        #pragma unroll
        for (int off=8; off; off>>=1){
            a0 += __shfl_xor_sync(0xffffffffu, a0, off);
            a1 += __shfl_xor_sync(0xffffffffu, a1, off);
        }
        if (g == 0){
            float l0 = a0 + b20, l1 = a1 + b21;
            float m = fmaxf(l0, l1);
            float e0 = __expf(l0 - m), e1 = __expf(l1 - m);
            float inv = 1.0f/(e0 + e1);
            ((float2*)out)[ebase + r] = make_float2(e0*inv, e1*inv);
        }
    }
}

extern "C" void kernel_launch(void* const* d_in, const int* in_sizes, int n_in,
                              void* d_out, int out_size){
    const int*   at   = (const int*)  d_in[0];
    const float* dist = (const float*)d_in[1];
    // d_in[2]=src, d_in[3]=dst (recomputed analytically; complete graph)
    const float* emb  = (const float*)d_in[4];
    const float* w1   = (const float*)d_in[5];
    const float* pw1  = (const float*)d_in[6];
    const float* pb1  = (const float*)d_in[7];
    const float* pw2  = (const float*)d_in[8];
    const float* pb2  = (const float*)d_in[9];
    const float* qw1  = (const float*)d_in[10];
    const float* qb1  = (const float*)d_in[11];
    const float* qw2  = (const float*)d_in[12];
    const float* qb2  = (const float*)d_in[13];
    const float* auw1 = (const float*)d_in[14];
    const float* aub1 = (const float*)d_in[15];
    const float* auw2 = (const float*)d_in[16];
    const float* aub2 = (const float*)d_in[17];
    const float* row1 = (const float*)d_in[18];
    const float* rob1 = (const float*)d_in[19];
    const float* row2 = (const float*)d_in[20];
    const float* rob2 = (const float*)d_in[21];
    float* out = (float*)d_out;

    cudaFuncSetAttribute(k_upd, cudaFuncAttributeMaxDynamicSharedMemorySize, SMEM_UPD);

    // launch index for ncu -s 5: 0:pre 1:msg 2:upd 3:msg 4:upd 5:msg <- profiled
    k_pre<<<TABM + TABRO + N_ATOMS, 64>>>(pw1, pb1, pw2, pb2, row1, rob1, at, emb, w1);
    for (int l = 0; l < 3; l++){
        k_msg<<<dim3(48, NSPLIT), 256>>>(dist, l);
        k_upd<<<192, 256, SMEM_UPD>>>(l, (l==2) ? 1 : 0, qw1, qb1, qw2, qb2, w1,
                                      auw1, aub1, auw2, aub2);
    }
    k_readout<<<N_ATOMS, 256>>>(dist, row1, row2, rob2, out);
}